// round 6
// baseline (speedup 1.0000x reference)
#include <cuda_runtime.h>
#include <float.h>
#include <stdint.h>

// Problem constants
#define KC      1024        // num codes
#define DD      64          // embedding dim
#define NTOK    65536       // 16*64*64 tokens
#define HW      4096        // 64*64
#define DECAYF  0.99f
#define OMDF    0.01f       // 1 - decay
#define COMMITF 0.25f
#define EPSF    1e-5f

// Output layout (flattened tuple, in reference return order)
#define OFF_LOSS 0ull
#define OFF_Q    1ull
#define OFF_ENC  (1ull + 4194304ull)
#define OFF_EMB  (OFF_ENC + 67108864ull)
#define OFF_CS   (OFF_EMB + 65536ull)
#define OFF_EMA  (OFF_CS + 1024ull)

// Scratch (no allocations allowed -> __device__ globals)
__device__ float g_counts[KC];
__device__ float g_dw[KC * DD];
__device__ float g_enorm[KC];
__device__ float g_loss;
__device__ float g_nsum;

// ---- packed f32x2 helpers ----
__device__ __forceinline__ unsigned long long pack2(float a, float b) {
    unsigned long long v;
    asm("mov.b64 %0, {%1, %2};" : "=l"(v) : "f"(a), "f"(b));
    return v;
}
__device__ __forceinline__ float2 unpack2(unsigned long long v) {
    float2 r;
    asm("mov.b64 {%0, %1}, %2;" : "=f"(r.x), "=f"(r.y) : "l"(v));
    return r;
}
#define FFMA2(d, a, b, c) \
    asm("fma.rn.f32x2 %0, %1, %2, %3;" : "=l"(d) : "l"(a), "l"(b), "l"(c))

// ================= K0: zero scratch + codebook norms =================
__global__ void vq_init(const float* __restrict__ E) {
    int i = blockIdx.x * blockDim.x + threadIdx.x;   // 65536 threads
    g_dw[i] = 0.f;
    if (i < KC) {
        g_counts[i] = 0.f;
        const float4* e4 = (const float4*)(E + (size_t)i * DD);
        float s = 0.f;
#pragma unroll
        for (int q = 0; q < 16; q++) {
            float4 v = e4[q];
            s += v.x * v.x + v.y * v.y + v.z * v.z + v.w * v.w;
        }
        g_enorm[i] = s;
    }
    if (i == 0) g_loss = 0.f;
}

// ================= K1: main — argmin + all heavy outputs =================
// 512 CTAs x 128 threads; thread t owns token n0+t.
__global__ __launch_bounds__(128, 4) void vq_main(
    const float* __restrict__ x,    // NCHW [16,64,64,64]
    const float* __restrict__ E,    // [1024,64]
    float* __restrict__ out)
{
    __shared__ float sE[128 * DD];   // 32 KB codebook chunk
    __shared__ float sNorm[128];
    __shared__ int   sIdx[128];
    __shared__ float sRed[4];

    const int t   = threadIdx.x;
    const int n0  = blockIdx.x * 128;
    const int b   = n0 >> 12;          // /4096
    const int hw0 = n0 & 4095;

    // ---- load this token's x row into packed registers (coalesced per-c) ----
    const float* xg = x + ((size_t)b * DD) * HW + hw0 + t;
    unsigned long long xr[32];
#pragma unroll
    for (int i = 0; i < 32; i++) {
        float lo = xg[(size_t)(2 * i) * HW];
        float hi = xg[(size_t)(2 * i + 1) * HW];
        xr[i] = pack2(lo, hi);
    }

    // ---- argmin over 8 chunks of 128 codes ----
    float best = FLT_MAX;
    int   bidx = 0;
    for (int ch = 0; ch < 8; ch++) {
        const float4* src = (const float4*)(E + (size_t)ch * 128 * DD);
        float4* dst = (float4*)sE;
#pragma unroll
        for (int i = 0; i < 16; i++) dst[t + i * 128] = src[t + i * 128];
        sNorm[t] = g_enorm[ch * 128 + t];
        __syncthreads();

#pragma unroll 2
        for (int c = 0; c < 128; c++) {
            const ulonglong2* ep = (const ulonglong2*)(sE + c * DD);
            unsigned long long a0 = 0ull, a1 = 0ull;  // (0.f,0.f)
#pragma unroll
            for (int q = 0; q < 16; q++) {
                ulonglong2 ev = ep[q];        // broadcast LDS.128
                FFMA2(a0, xr[2 * q],     ev.x, a0);
                FFMA2(a1, xr[2 * q + 1], ev.y, a1);
            }
            float2 f0 = unpack2(a0), f1 = unpack2(a1);
            float dot = (f0.x + f0.y) + (f1.x + f1.y);
            float score = sNorm[c] - 2.0f * dot;   // ||e||^2 - 2 x.e
            if (score < best) { best = score; bidx = ch * 128 + c; }
        }
        __syncthreads();
    }

    sIdx[t] = bidx;
    atomicAdd(&g_counts[bidx], 1.0f);

    // ---- per-token epilogue: quantized out (NCHW), loss partial, dw scatter ----
    const float4* erow = (const float4*)(E + (size_t)bidx * DD);
    float* qout = out + OFF_Q + ((size_t)b * DD) * HW + hw0 + t;
    float* dwp  = g_dw + (size_t)bidx * DD;
    float lsum = 0.f;
#pragma unroll
    for (int q4 = 0; q4 < 16; q4++) {
        float4 ev = __ldg(erow + q4);      // scattered, L2-hot (E = 256KB)
        float2 xa = unpack2(xr[2 * q4]);
        float2 xb = unpack2(xr[2 * q4 + 1]);
        int d = q4 * 4;
        qout[(size_t)(d + 0) * HW] = ev.x;
        qout[(size_t)(d + 1) * HW] = ev.y;
        qout[(size_t)(d + 2) * HW] = ev.z;
        qout[(size_t)(d + 3) * HW] = ev.w;
        float d0 = ev.x - xa.x, d1 = ev.y - xa.y;
        float d2 = ev.z - xb.x, d3 = ev.w - xb.y;
        lsum += d0 * d0 + d1 * d1 + d2 * d2 + d3 * d3;
        atomicAdd(dwp + d + 0, xa.x);
        atomicAdd(dwp + d + 1, xa.y);
        atomicAdd(dwp + d + 2, xb.x);
        atomicAdd(dwp + d + 3, xb.y);
    }

    // block-reduce commitment-loss partial
#pragma unroll
    for (int o = 16; o > 0; o >>= 1) lsum += __shfl_xor_sync(0xffffffffu, lsum, o);
    if ((t & 31) == 0) sRed[t >> 5] = lsum;
    __syncthreads();   // also publishes sIdx[] for the encodings pass
    if (t == 0) atomicAdd(&g_loss, sRed[0] + sRed[1] + sRed[2] + sRed[3]);

    // ---- cooperative one-hot encodings write: 128 tokens x 1024 cols ----
    // out + OFF_ENC is offset 1 float mod 16B, so each GLOBAL token row
    // (n0+tok)*1024 is vector-alignable only from col 3:
    // (1 + row*1024 + 3) % 4 == 0. Per token: cols [3,1023) as 255 float4,
    // cols {0,1,2,1023} scalar.
    {
        float* encb = out + OFF_ENC;
#pragma unroll 4
        for (int i = t; i < 128 * 256; i += 128) {
            int tok = i >> 8;
            int q   = i & 255;
            int id  = sIdx[tok];
            float* row = encb + (size_t)(n0 + tok) * KC;   // GLOBAL token row
            if (q < 255) {
                int c0 = 3 + q * 4;
                float4 v;
                v.x = (float)(c0 + 0 == id);
                v.y = (float)(c0 + 1 == id);
                v.z = (float)(c0 + 2 == id);
                v.w = (float)(c0 + 3 == id);
                __stcs((float4*)(row + c0), v);
            } else {
                __stcs(row + 0,    (float)(id == 0));
                __stcs(row + 1,    (float)(id == 1));
                __stcs(row + 2,    (float)(id == 2));
                __stcs(row + 1023, (float)(id == 1023));
            }
        }
    }
}

// ================= K2: EMA cluster-size raw + global sum n =================
__global__ void vq_reduce(const float* __restrict__ ema_cs) {
    int k = threadIdx.x;   // 1024 threads, 1 block
    float raw = ema_cs[k] * DECAYF + OMDF * g_counts[k];
    g_counts[k] = raw;     // reuse scratch for raw new_cs
    __shared__ float wsum[32];
    float s = raw;
#pragma unroll
    for (int o = 16; o > 0; o >>= 1) s += __shfl_xor_sync(0xffffffffu, s, o);
    if ((k & 31) == 0) wsum[k >> 5] = s;
    __syncthreads();
    if (k < 32) {
        float v = wsum[k];
#pragma unroll
        for (int o = 16; o > 0; o >>= 1) v += __shfl_xor_sync(0xffffffffu, v, o);
        if (k == 0) g_nsum = v;
    }
}

// ================= K3: finalize codebook outputs + loss =================
__global__ void vq_final(const float* __restrict__ ema_w, float* __restrict__ out) {
    int i = blockIdx.x * blockDim.x + threadIdx.x;   // 65536 = K*D
    int k = i >> 6;
    int d = i & 63;
    float n   = g_nsum;
    float raw = g_counts[k];
    float cs  = (raw + EPSF) / (n + (float)KC * EPSF) * n;  // Laplace smoothing
    float nw  = ema_w[i] * DECAYF + OMDF * g_dw[i];
    out[OFF_EMA + i] = nw;
    out[OFF_EMB + i] = nw / cs;
    if (d == 0) out[OFF_CS + k] = cs;
    if (i == 0) out[OFF_LOSS] = COMMITF * g_loss / 4194304.0f;
}

// ================= launch =================
extern "C" void kernel_launch(void* const* d_in, const int* in_sizes, int n_in,
                              void* d_out, int out_size) {
    const float* x      = (const float*)d_in[0];   // [16,64,64,64]
    const float* E      = (const float*)d_in[1];   // [1024,64]
    const float* ema_cs = (const float*)d_in[2];   // [1024]
    const float* ema_w  = (const float*)d_in[3];   // [1024,64]
    float* out = (float*)d_out;

    vq_init<<<256, 256>>>(E);
    vq_main<<<NTOK / 128, 128>>>(x, E, out);
    vq_reduce<<<1, 1024>>>(ema_cs);
    vq_final<<<64, 1024>>>(ema_w, out);
}

// round 8
// speedup vs baseline: 1.2591x; 1.2591x over previous
#include <cuda_runtime.h>
#include <float.h>
#include <stdint.h>

// Problem constants
#define KC      1024        // num codes
#define DD      64          // embedding dim
#define NTOK    65536       // 16*64*64 tokens
#define HW      4096        // 64*64
#define DECAYF  0.99f
#define OMDF    0.01f       // 1 - decay
#define COMMITF 0.25f
#define EPSF    1e-5f

// Output layout (flattened tuple, in reference return order)
#define OFF_LOSS 0ull
#define OFF_Q    1ull
#define OFF_ENC  (1ull + 4194304ull)
#define OFF_EMB  (OFF_ENC + 67108864ull)
#define OFF_CS   (OFF_EMB + 65536ull)
#define OFF_EMA  (OFF_CS + 1024ull)

// Dynamic smem layout (bytes)
#define SM_XS     0        // 4096 u64  (32 dpairs x 128 tokens)  32768 B
#define SM_ES     32768    // 128 codes x 68 floats (64 used)     34816 B
#define SM_NORM   67584    // 128 floats
#define SM_SCORE  68096    // 128 tokens x 8 tx floats            4096 B
#define SM_SIDX   72192    // 128 x 8 ints                        4096 B
#define SM_IDXF   76288    // 128 ints
#define SM_RED    76800    // 4 floats
#define SM_TOTAL  76816

// Scratch (no allocations allowed -> __device__ globals)
__device__ float g_counts[KC];
__device__ float g_dw[KC * DD];
__device__ float g_enorm[KC];
__device__ float g_loss;
__device__ float g_nsum;

// ---- packed f32x2 helpers ----
__device__ __forceinline__ unsigned long long pack2(float a, float b) {
    unsigned long long v;
    asm("mov.b64 %0, {%1, %2};" : "=l"(v) : "f"(a), "f"(b));
    return v;
}
__device__ __forceinline__ float2 unpack2(unsigned long long v) {
    float2 r;
    asm("mov.b64 {%0, %1}, %2;" : "=f"(r.x), "=f"(r.y) : "l"(v));
    return r;
}
#define FFMA2(d, a, b, c) \
    asm("fma.rn.f32x2 %0, %1, %2, %3;" : "=l"(d) : "l"(a), "l"(b), "l"(c))

// ================= K0: zero scratch + codebook norms =================
__global__ void vq_init(const float* __restrict__ E) {
    int i = blockIdx.x * blockDim.x + threadIdx.x;   // 65536 threads
    g_dw[i] = 0.f;
    if (i < KC) {
        g_counts[i] = 0.f;
        const float4* e4 = (const float4*)(E + (size_t)i * DD);
        float s = 0.f;
#pragma unroll
        for (int q = 0; q < 16; q++) {
            float4 v = e4[q];
            s += v.x * v.x + v.y * v.y + v.z * v.z + v.w * v.w;
        }
        g_enorm[i] = s;
    }
    if (i == 0) g_loss = 0.f;
}

// ================= K1: main — register-tiled argmin GEMM + outputs ===========
// 512 CTAs x 128 threads; CTA owns 128 tokens. Thread (ty,tx): ty=t>>3 token
// group (8 tokens), tx=t&7 code group. 8x4 accumulator tile in packed f32x2.
__global__ __launch_bounds__(128, 2) void vq_main(
    const float* __restrict__ x,    // NCHW [16,64,64,64]
    const float* __restrict__ E,    // [1024,64]
    float* __restrict__ out)
{
    extern __shared__ char smem[];
    unsigned long long* xs = (unsigned long long*)(smem + SM_XS);
    float* es    = (float*)(smem + SM_ES);
    float* sNorm = (float*)(smem + SM_NORM);
    float* sScore= (float*)(smem + SM_SCORE);
    int*   sSIdx = (int*)  (smem + SM_SIDX);
    int*   sIdxF = (int*)  (smem + SM_IDXF);
    float* sRed  = (float*)(smem + SM_RED);

    const int t   = threadIdx.x;
    const int tx  = t & 7;
    const int ty  = t >> 3;
    const int n0  = blockIdx.x * 128;
    const int b   = n0 >> 12;          // /4096
    const int hw0 = n0 & 4095;

    // ---- stage x tile into smem, dpair-major: xs[dp*128 + tok] ----
    const float* xg = x + ((size_t)b * DD) * HW + hw0 + t;
#pragma unroll
    for (int dp = 0; dp < 32; dp++) {
        float lo = xg[(size_t)(2 * dp) * HW];
        float hi = xg[(size_t)(2 * dp + 1) * HW];
        xs[dp * 128 + t] = pack2(lo, hi);
    }

    float best[8];
    int   bidx[8];
#pragma unroll
    for (int i = 0; i < 8; i++) { best[i] = FLT_MAX; bidx[i] = 0; }

    // ---- 8 chunks of 128 codes ----
    for (int ch = 0; ch < 8; ch++) {
        __syncthreads();   // protect es/sNorm from previous chunk's readers
        const float4* src = (const float4*)(E + (size_t)ch * 128 * DD);
#pragma unroll
        for (int i2 = 0; i2 < 16; i2++) {
            int f = t + i2 * 128;            // 2048 float4 of the chunk
            int code = f >> 4, q = f & 15;
            *(float4*)&es[code * 68 + q * 4] = src[f];   // padded rows: 68 floats
        }
        sNorm[t] = g_enorm[ch * 128 + t];
        __syncthreads();

        for (int cc = 0; cc < 4; cc++) {          // 32 codes per pass
            unsigned long long acc[8][4];
#pragma unroll
            for (int i = 0; i < 8; i++)
#pragma unroll
                for (int j = 0; j < 4; j++) acc[i][j] = 0ull;

            const int cbase = cc * 32 + tx;       // code(j) = cbase + j*8

#pragma unroll 4
            for (int dq = 0; dq < 16; dq++) {     // d-quad = 4 dims = 2 dpairs
                unsigned long long xa0[8], xa1[8], eb0[4], eb1[4];
#pragma unroll
                for (int k = 0; k < 4; k++) {
                    ulonglong2 v0 = *(const ulonglong2*)&xs[(2 * dq)     * 128 + ty * 8 + 2 * k];
                    ulonglong2 v1 = *(const ulonglong2*)&xs[(2 * dq + 1) * 128 + ty * 8 + 2 * k];
                    xa0[2 * k] = v0.x; xa0[2 * k + 1] = v0.y;
                    xa1[2 * k] = v1.x; xa1[2 * k + 1] = v1.y;
                }
#pragma unroll
                for (int j = 0; j < 4; j++) {
                    ulonglong2 ev = *(const ulonglong2*)&es[(cbase + j * 8) * 68 + dq * 4];
                    eb0[j] = ev.x; eb1[j] = ev.y;
                }
#pragma unroll
                for (int i = 0; i < 8; i++)
#pragma unroll
                    for (int j = 0; j < 4; j++) {
                        FFMA2(acc[i][j], xa0[i], eb0[j], acc[i][j]);
                        FFMA2(acc[i][j], xa1[i], eb1[j], acc[i][j]);
                    }
            }

            // scores + per-token best (codes ascend within thread: strict <)
#pragma unroll
            for (int j = 0; j < 4; j++) {
                const int code = cbase + j * 8;
                const float nrm = sNorm[code];
#pragma unroll
                for (int i = 0; i < 8; i++) {
                    float2 f = unpack2(acc[i][j]);
                    float score = nrm - 2.0f * (f.x + f.y);
                    if (score < best[i]) { best[i] = score; bidx[i] = ch * 128 + code; }
                }
            }
        }
    }

    // ---- cross-tx argmin reduction per token ----
#pragma unroll
    for (int i = 0; i < 8; i++) {
        sScore[(ty * 8 + i) * 8 + tx] = best[i];
        sSIdx [(ty * 8 + i) * 8 + tx] = bidx[i];
    }
    __syncthreads();
    float bsc = sScore[t * 8];
    int   bid = sSIdx [t * 8];
#pragma unroll
    for (int u = 1; u < 8; u++) {
        float s = sScore[t * 8 + u];
        int   d = sSIdx [t * 8 + u];
        if (s < bsc || (s == bsc && d < bid)) { bsc = s; bid = d; }
    }
    sIdxF[t] = bid;
    atomicAdd(&g_counts[bid], 1.0f);

    // ---- per-token epilogue: quantized out (NCHW), loss partial, dw scatter ----
    const float4* erow = (const float4*)(E + (size_t)bid * DD);
    float* qout = out + OFF_Q + ((size_t)b * DD) * HW + hw0 + t;
    float* dwp  = g_dw + (size_t)bid * DD;
    float lsum = 0.f;
#pragma unroll
    for (int q4 = 0; q4 < 16; q4++) {
        float4 ev = __ldg(erow + q4);      // scattered, L2-hot (E = 256KB)
        float2 xa = unpack2(xs[(2 * q4)     * 128 + t]);
        float2 xb = unpack2(xs[(2 * q4 + 1) * 128 + t]);
        int d = q4 * 4;
        qout[(size_t)(d + 0) * HW] = ev.x;
        qout[(size_t)(d + 1) * HW] = ev.y;
        qout[(size_t)(d + 2) * HW] = ev.z;
        qout[(size_t)(d + 3) * HW] = ev.w;
        float d0 = ev.x - xa.x, d1 = ev.y - xa.y;
        float d2 = ev.z - xb.x, d3 = ev.w - xb.y;
        lsum += d0 * d0 + d1 * d1 + d2 * d2 + d3 * d3;
        atomicAdd(dwp + d + 0, xa.x);
        atomicAdd(dwp + d + 1, xa.y);
        atomicAdd(dwp + d + 2, xb.x);
        atomicAdd(dwp + d + 3, xb.y);
    }

    // block-reduce commitment-loss partial
#pragma unroll
    for (int o = 16; o > 0; o >>= 1) lsum += __shfl_xor_sync(0xffffffffu, lsum, o);
    if ((t & 31) == 0) sRed[t >> 5] = lsum;
    __syncthreads();
    if (t == 0) atomicAdd(&g_loss, sRed[0] + sRed[1] + sRed[2] + sRed[3]);

    // ---- cooperative one-hot encodings write: 128 tokens x 1024 cols ----
    // out + OFF_ENC is offset 1 float mod 16B, so each GLOBAL token row
    // (n0+tok)*1024 is vector-alignable only from col 3. Per token:
    // cols [3,1023) as 255 float4, cols {0,1,2,1023} scalar.
    {
        float* encb = out + OFF_ENC;
#pragma unroll 4
        for (int i = t; i < 128 * 256; i += 128) {
            int tok = i >> 8;
            int q   = i & 255;
            int id  = sIdxF[tok];
            float* row = encb + (size_t)(n0 + tok) * KC;   // GLOBAL token row
            if (q < 255) {
                int c0 = 3 + q * 4;
                float4 v;
                v.x = (float)(c0 + 0 == id);
                v.y = (float)(c0 + 1 == id);
                v.z = (float)(c0 + 2 == id);
                v.w = (float)(c0 + 3 == id);
                __stcs((float4*)(row + c0), v);
            } else {
                __stcs(row + 0,    (float)(id == 0));
                __stcs(row + 1,    (float)(id == 1));
                __stcs(row + 2,    (float)(id == 2));
                __stcs(row + 1023, (float)(id == 1023));
            }
        }
    }
}

// ================= K2: EMA cluster-size raw + global sum n =================
__global__ void vq_reduce(const float* __restrict__ ema_cs) {
    int k = threadIdx.x;   // 1024 threads, 1 block
    float raw = ema_cs[k] * DECAYF + OMDF * g_counts[k];
    g_counts[k] = raw;     // reuse scratch for raw new_cs
    __shared__ float wsum[32];
    float s = raw;
#pragma unroll
    for (int o = 16; o > 0; o >>= 1) s += __shfl_xor_sync(0xffffffffu, s, o);
    if ((k & 31) == 0) wsum[k >> 5] = s;
    __syncthreads();
    if (k < 32) {
        float v = wsum[k];
#pragma unroll
        for (int o = 16; o > 0; o >>= 1) v += __shfl_xor_sync(0xffffffffu, v, o);
        if (k == 0) g_nsum = v;
    }
}

// ================= K3: finalize codebook outputs + loss =================
__global__ void vq_final(const float* __restrict__ ema_w, float* __restrict__ out) {
    int i = blockIdx.x * blockDim.x + threadIdx.x;   // 65536 = K*D
    int k = i >> 6;
    int d = i & 63;
    float n   = g_nsum;
    float raw = g_counts[k];
    float cs  = (raw + EPSF) / (n + (float)KC * EPSF) * n;  // Laplace smoothing
    float nw  = ema_w[i] * DECAYF + OMDF * g_dw[i];
    out[OFF_EMA + i] = nw;
    out[OFF_EMB + i] = nw / cs;
    if (d == 0) out[OFF_CS + k] = cs;
    if (i == 0) out[OFF_LOSS] = COMMITF * g_loss / 4194304.0f;
}

// ================= launch =================
extern "C" void kernel_launch(void* const* d_in, const int* in_sizes, int n_in,
                              void* d_out, int out_size) {
    const float* x      = (const float*)d_in[0];   // [16,64,64,64]
    const float* E      = (const float*)d_in[1];   // [1024,64]
    const float* ema_cs = (const float*)d_in[2];   // [1024]
    const float* ema_w  = (const float*)d_in[3];   // [1024,64]
    float* out = (float*)d_out;

    cudaFuncSetAttribute(vq_main, cudaFuncAttributeMaxDynamicSharedMemorySize, SM_TOTAL);

    vq_init<<<256, 256>>>(E);
    vq_main<<<NTOK / 128, 128, SM_TOTAL>>>(x, E, out);
    vq_reduce<<<1, 1024>>>(ema_cs);
    vq_final<<<64, 1024>>>(ema_w, out);
}